// round 17
// baseline (speedup 1.0000x reference)
#include <cuda_runtime.h>
#include <cuda_fp16.h>
#include <stdint.h>

// Flash attention, B=32, LQ=LK=2048, D=128, fp32 in/out. HMMA path.
// Mask: 4-byte elems (bool promoted); nonzero = masked. score=(q.k)*sqrt(128).
// QK^T: fp16 hi/lo 3-term MMA (K2 folded into Q). PV: single-term fp16.
// R16 = R15 with the mask-staging bug fixed (one lane = one row, 32 rows/warp).
// 8 warps = 4 row-groups x 2 key-half warps; K and V smem reads per warp
// halved (-31% crossbar bytes); max/sum combined via smem; P via smem tile.

namespace {

constexpr int B_   = 32;
constexpr int LQ_  = 2048;
constexpr int LK_  = 2048;
constexpr int DH   = 128;
constexpr int BR   = 128;
constexpr int BC   = 64;
constexpr int NTH  = 256;   // 8 warps
constexpr int NIT  = LK_ / BC;
constexpr int RSB  = 272;   // 128 fp16 + 16B pad

constexpr int PLANE  = BC * RSB;        // 17408 (64-key plane)
constexpr int QPLANE = BR * RSB;        // 34816
constexpr int KSTG   = 2 * PLANE;       // K hi+lo per stage

constexpr int SM_QHI = 0;                        // persistent Q hi
constexpr int SM_QLO = QPLANE;                   // persistent Q lo
constexpr int SM_K   = 2 * QPLANE;               // 2 K stages -> +69632
constexpr int SM_V   = SM_K + 2 * KSTG;          // 2 V planes -> +34816
constexpr int SM_P   = SM_V + 2 * PLANE;         // P tile 128 x 64 fp16
constexpr int PRSB   = 144;                      // 64 fp16 + 16 pad
constexpr int SM_MX  = SM_P + BR * PRSB;         // [4 rg][2 kh][32] f32 = 1024
constexpr int SM_SU  = SM_MX + 1024;             // same shape
constexpr int SM_MSK = SM_SU + 1024;             // per warp 32 rows x 36B
constexpr int MROW2  = 36;
constexpr int SM_TOT = SM_MSK + 8 * 32 * MROW2;  // 203776 B

__device__ __half g_khi[(size_t)B_ * LK_ * DH];
__device__ __half g_klo[(size_t)B_ * LK_ * DH];
__device__ __half g_vh [(size_t)B_ * LK_ * DH];

__device__ __forceinline__ uint32_t smem_u32(const void* p) {
    return (uint32_t)__cvta_generic_to_shared(p);
}
__device__ __forceinline__ void cp16(uint32_t dst, const void* src) {
    asm volatile("cp.async.cg.shared.global [%0], [%1], 16;" :: "r"(dst), "l"(src));
}
#define CP_COMMIT() asm volatile("cp.async.commit_group;")
#define CP_WAIT0()  asm volatile("cp.async.wait_group 0;")

__device__ __forceinline__ void ldsm4(uint32_t r[4], uint32_t a) {
    asm volatile("ldmatrix.sync.aligned.m8n8.x4.shared.b16 {%0,%1,%2,%3}, [%4];"
                 : "=r"(r[0]), "=r"(r[1]), "=r"(r[2]), "=r"(r[3]) : "r"(a));
}
__device__ __forceinline__ void ldsm4t(uint32_t r[4], uint32_t a) {
    asm volatile("ldmatrix.sync.aligned.m8n8.x4.trans.shared.b16 {%0,%1,%2,%3}, [%4];"
                 : "=r"(r[0]), "=r"(r[1]), "=r"(r[2]), "=r"(r[3]) : "r"(a));
}
__device__ __forceinline__ void mma_f16(float d[4], const uint32_t a[4], uint32_t b0, uint32_t b1) {
    asm volatile("mma.sync.aligned.m16n8k16.row.col.f32.f16.f16.f32 "
                 "{%0,%1,%2,%3}, {%4,%5,%6,%7}, {%8,%9}, {%0,%1,%2,%3};"
                 : "+f"(d[0]), "+f"(d[1]), "+f"(d[2]), "+f"(d[3])
                 : "r"(a[0]), "r"(a[1]), "r"(a[2]), "r"(a[3]), "r"(b0), "r"(b1));
}
__device__ __forceinline__ float ex2f(float x) {
    float y; asm("ex2.approx.f32 %0, %1;" : "=f"(y) : "f"(x)); return y;
}
__device__ __forceinline__ uint32_t pack_h2(float x, float y) {
    uint32_t r;
    asm("cvt.rn.f16x2.f32 %0, %1, %2;" : "=r"(r) : "f"(y), "f"(x));
    return r;
}
__device__ __forceinline__ void split_store_hs(float4 f, float sc, char* ph, char* pl) {
    float x = f.x * sc, y = f.y * sc, z = f.z * sc, w = f.w * sc;
    __half h0 = __float2half_rn(x);
    __half h1 = __float2half_rn(y);
    __half h2 = __float2half_rn(z);
    __half h3 = __float2half_rn(w);
    *(__half2*)(ph)     = __halves2half2(h0, h1);
    *(__half2*)(ph + 4) = __halves2half2(h2, h3);
    __half l0 = __float2half_rn(x - __half2float(h0));
    __half l1 = __float2half_rn(y - __half2float(h1));
    __half l2 = __float2half_rn(z - __half2float(h2));
    __half l3 = __float2half_rn(w - __half2float(h3));
    *(__half2*)(pl)     = __halves2half2(l0, l1);
    *(__half2*)(pl + 4) = __halves2half2(l2, l3);
}

__global__ void __launch_bounds__(256, 4)
conv_kernel(const float* __restrict__ kg, const float* __restrict__ vg)
{
    size_t i4 = ((size_t)blockIdx.x * 256 + threadIdx.x) * 4;
    float4 fk = *(const float4*)(kg + i4);
    split_store_hs(fk, 1.0f, (char*)(g_khi + i4), (char*)(g_klo + i4));
    float4 fv = *(const float4*)(vg + i4);
    *(__half2*)(g_vh + i4)     = __halves2half2(__float2half_rn(fv.x), __float2half_rn(fv.y));
    *(__half2*)(g_vh + i4 + 2) = __halves2half2(__float2half_rn(fv.z), __float2half_rn(fv.w));
}

__global__ void __launch_bounds__(NTH, 1)
fa_r16_kernel(const float* __restrict__ qg, const uint32_t* __restrict__ mg,
              float* __restrict__ og)
{
    extern __shared__ char smem[];
    const int tid  = threadIdx.x;
    const int lane = tid & 31;
    const int warp = tid >> 5;
    const int rg   = warp >> 1;      // row group 0..3 (rows rg*32..+31)
    const int kh   = warp & 1;       // key half (QK) / dim half (PV)
    const int R0   = rg * 32;
    const int b    = blockIdx.y;
    const int q0   = blockIdx.x * BR;

    const float K2  = 16.3222312f;   // sqrt(128)*log2(e), folded into Q
    const float NEG = -1e30f;
    const float BIG = 3e38f;
    const uint32_t sm0 = smem_u32(smem);

    // ---- fill helpers (start K/V(0) immediately; regions are disjoint) ----
    const size_t kvoff0 = (size_t)b * LK_ * DH;
    auto fill_K = [&](int kt2) {
        size_t off = kvoff0 + (size_t)kt2 * BC * DH;
        uint32_t dst0 = sm0 + (uint32_t)(SM_K + (kt2 & 1) * KSTG);
        #pragma unroll
        for (int i = 0; i < 8; ++i) {
            int idx = tid + i * NTH;          // 0..2047
            int p = idx >> 10, r = (idx >> 4) & 63, c = idx & 15;
            const __half* src = (p == 0 ? g_khi : g_klo) + off + (size_t)r * DH + c * 8;
            cp16(dst0 + (uint32_t)(p * PLANE + r * RSB + c * 16), src);
        }
    };
    auto fill_V = [&](int kt2) {
        size_t off = kvoff0 + (size_t)kt2 * BC * DH;
        uint32_t dst0 = sm0 + (uint32_t)(SM_V + (kt2 & 1) * PLANE);
        #pragma unroll
        for (int i = 0; i < 4; ++i) {
            int idx = tid + i * NTH;          // 0..1023
            int r = (idx >> 4) & 63, c = idx & 15;
            cp16(dst0 + (uint32_t)(r * RSB + c * 16), g_vh + off + (size_t)r * DH + c * 8);
        }
    };
    fill_K(0);
    fill_V(0);
    CP_COMMIT();

    // ---- Q tile * K2 -> fp16 hi/lo persistent smem ----
    {
        const float* qp = qg + ((size_t)b * LQ_ + q0) * DH;
        #pragma unroll
        for (int i = 0; i < 16; ++i) {
            int idx = tid + i * NTH;          // 4096 float4
            int row = idx >> 5, c4 = idx & 31;
            float4 f = *(const float4*)(qp + (size_t)row * DH + c4 * 4);
            split_store_hs(f, K2, smem + SM_QHI + row * RSB + c4 * 8,
                                  smem + SM_QLO + row * RSB + c4 * 8);
        }
    }

    // ---- mask prefetch: one lane = one row (R0+lane), keys kh*32..+31 ----
    const uint32_t* mp_row = mg + (size_t)b * LQ_ * LK_
                           + (size_t)(q0 + R0 + lane) * LK_ + kh * 32;
    uint32_t pk[8];
    auto ldgm = [&](int kt2) {
        const uint32_t* mp = mp_row + (size_t)kt2 * BC;
        #pragma unroll
        for (int j = 0; j < 8; ++j) {
            uint4 m = *(const uint4*)(mp + j * 4);
            pk[j] = (m.x ? 1u : 0u) | ((m.y ? 1u : 0u) << 8) |
                    ((m.z ? 1u : 0u) << 16) | ((m.w ? 1u : 0u) << 24);
        }
    };
    ldgm(0);
    __syncthreads();   // Q visible

    // qa_hi persistent: [kb 0..7][mf 0..1][4]; qa_lo streamed from smem
    uint32_t qa_hi[8][2][4];
    uint32_t qfrag[2];
    #pragma unroll
    for (int mf = 0; mf < 2; ++mf) {
        qfrag[mf] = sm0 + (uint32_t)((R0 + mf * 16 + (lane & 15)) * RSB + (lane >> 4) * 16);
        #pragma unroll
        for (int kb = 0; kb < 8; ++kb) ldsm4(qa_hi[kb][mf], qfrag[mf] + SM_QHI + kb * 32);
    }

    float acc[16][4];   // [mf*8 + dimfrag]: 32 rows x 64 dims (kh half)
    #pragma unroll
    for (int j = 0; j < 16; ++j) { acc[j][0]=0.f; acc[j][1]=0.f; acc[j][2]=0.f; acc[j][3]=0.f; }
    float mo[2][2] = {{NEG,NEG},{NEG,NEG}};   // [mf][h] running max
    float lr[2][2] = {{0.f,0.f},{0.f,0.f}};   // [mf][h] running sum

    const int r0q = lane >> 2;                // row within frag (+8 for h=1)
    const uint32_t kf_l = sm0 + (uint32_t)SM_K
                        + (uint32_t)((lane & 7) * RSB + (lane >> 3) * 16 + kh * 32 * RSB);
    const uint32_t vf_l = sm0 + (uint32_t)SM_V
                        + (uint32_t)((lane & 15) * RSB + (lane >> 4) * 16 + kh * 128);
    uint32_t pfrag[2];
    #pragma unroll
    for (int mf = 0; mf < 2; ++mf)
        pfrag[mf] = sm0 + (uint32_t)(SM_P + (R0 + mf * 16 + (lane & 15)) * PRSB + (lane >> 4) * 16);

    char* mskw = smem + SM_MSK + warp * (32 * MROW2) + lane * MROW2;
    const char* mrd = smem + SM_MSK + warp * (32 * MROW2);
    float* mxme = (float*)(smem + SM_MX) + (rg * 2 + kh) * 32;
    float* mxpr = (float*)(smem + SM_MX) + (rg * 2 + (kh ^ 1)) * 32;
    float* sume = (float*)(smem + SM_SU) + (rg * 2 + kh) * 32;
    float* supr = (float*)(smem + SM_SU) + (rg * 2 + (kh ^ 1)) * 32;

    #pragma unroll 1
    for (int kt = 0; kt < NIT; ++kt) {
        CP_WAIT0();
        __syncthreads();   // K/V(kt) ready; prev-iter P/V reads complete

        if (kt + 1 < NIT) { fill_K(kt + 1); fill_V(kt + 1); }
        CP_COMMIT();

        // stage mask(kt): one lane = one row (32 bytes), prefetch mask(kt+1)
        #pragma unroll
        for (int j = 0; j < 8; ++j) *(uint32_t*)(mskw + j * 4) = pk[j];
        __syncwarp();
        if (kt + 1 < NIT) ldgm(kt + 1);

        const uint32_t kfb = kf_l + (uint32_t)((kt & 1) * KSTG);

        // ---- S = Q K^T : 32 rows x 32 keys, fp16 hi/lo 3 terms ----
        float s[8][4];    // [mf*4 + nb]
        #pragma unroll
        for (int j = 0; j < 8; ++j) { s[j][0]=0.f; s[j][1]=0.f; s[j][2]=0.f; s[j][3]=0.f; }
        #pragma unroll
        for (int kp2 = 0; kp2 < 4; ++kp2) {
            const int kb0 = 2 * kp2, kb1 = 2 * kp2 + 1;
            uint32_t ql0[2][4], ql1[2][4];
            ldsm4(ql0[0], qfrag[0] + SM_QLO + kb0 * 32);
            ldsm4(ql0[1], qfrag[1] + SM_QLO + kb0 * 32);
            ldsm4(ql1[0], qfrag[0] + SM_QLO + kb1 * 32);
            ldsm4(ql1[1], qfrag[1] + SM_QLO + kb1 * 32);
            #pragma unroll
            for (int nb = 0; nb < 4; ++nb) {
                const uint32_t ka = kfb + (uint32_t)(nb * 8 * RSB + kp2 * 64);
                uint32_t bh[4], bl[4];
                ldsm4(bh, ka);
                ldsm4(bl, ka + PLANE);
                #pragma unroll
                for (int mf = 0; mf < 2; ++mf) {
                    const int idx = mf * 4 + nb;
                    mma_f16(s[idx], qa_hi[kb0][mf], bh[0], bh[1]);
                    mma_f16(s[idx], ql0[mf],        bh[0], bh[1]);
                    mma_f16(s[idx], qa_hi[kb1][mf], bh[2], bh[3]);
                    mma_f16(s[idx], ql1[mf],        bh[2], bh[3]);
                    mma_f16(s[idx], qa_hi[kb0][mf], bl[0], bl[1]);
                    mma_f16(s[idx], qa_hi[kb1][mf], bl[2], bl[3]);
                }
            }
        }

        // ---- mask, partial row max (this key half) ----
        float tm[2][2] = {{NEG,NEG},{NEG,NEG}};
        #pragma unroll
        for (int mf = 0; mf < 2; ++mf) {
            #pragma unroll
            for (int nb = 0; nb < 4; ++nb) {
                const int idx = mf * 4 + nb;
                int c = (nb << 3) + ((lane & 3) << 1);
                const char* m0 = mrd + (mf * 16 + r0q) * MROW2;
                const char* m1 = m0 + 8 * MROW2;
                uint32_t mm0 = *(const unsigned short*)(m0 + c);
                uint32_t mm1 = *(const unsigned short*)(m1 + c);
                s[idx][0] = (mm0 & 0xff) ? NEG : s[idx][0];
                s[idx][1] = (mm0 >> 8)   ? NEG : s[idx][1];
                s[idx][2] = (mm1 & 0xff) ? NEG : s[idx][2];
                s[idx][3] = (mm1 >> 8)   ? NEG : s[idx][3];
                tm[mf][0] = fmaxf(tm[mf][0], fmaxf(s[idx][0], s[idx][1]));
                tm[mf][1] = fmaxf(tm[mf][1], fmaxf(s[idx][2], s[idx][3]));
            }
            tm[mf][0] = fmaxf(tm[mf][0], __shfl_xor_sync(0xffffffffu, tm[mf][0], 1));
            tm[mf][0] = fmaxf(tm[mf][0], __shfl_xor_sync(0xffffffffu, tm[mf][0], 2));
            tm[mf][1] = fmaxf(tm[mf][1], __shfl_xor_sync(0xffffffffu, tm[mf][1], 1));
            tm[mf][1] = fmaxf(tm[mf][1], __shfl_xor_sync(0xffffffffu, tm[mf][1], 2));
        }
        if ((lane & 3) == 0) {
            mxme[r0q]      = tm[0][0];
            mxme[r0q + 8]  = tm[0][1];
            mxme[r0q + 16] = tm[1][0];
            mxme[r0q + 24] = tm[1][1];
        }
        __syncthreads();                        // max exchange
        tm[0][0] = fmaxf(tm[0][0], mxpr[r0q]);
        tm[0][1] = fmaxf(tm[0][1], mxpr[r0q + 8]);
        tm[1][0] = fmaxf(tm[1][0], mxpr[r0q + 16]);
        tm[1][1] = fmaxf(tm[1][1], mxpr[r0q + 24]);

        float aa[2][2], ms[2][2], su[2][2];
        #pragma unroll
        for (int mf = 0; mf < 2; ++mf)
            #pragma unroll
            for (int h = 0; h < 2; ++h) {
                float mn = fmaxf(mo[mf][h], tm[mf][h]);
                aa[mf][h] = ex2f(mo[mf][h] - mn);
                ms[mf][h] = (mn > NEG) ? mn : BIG;
                mo[mf][h] = mn;
                su[mf][h] = 0.f;
            }

        #pragma unroll
        for (int mf = 0; mf < 2; ++mf) {
            #pragma unroll
            for (int nb = 0; nb < 4; ++nb) {
                const int idx = mf * 4 + nb;
                s[idx][0] = ex2f(s[idx][0] - ms[mf][0]);
                s[idx][1] = ex2f(s[idx][1] - ms[mf][0]);
                s[idx][2] = ex2f(s[idx][2] - ms[mf][1]);
                s[idx][3] = ex2f(s[idx][3] - ms[mf][1]);
                su[mf][0] += s[idx][0] + s[idx][1];
                su[mf][1] += s[idx][2] + s[idx][3];
            }
            su[mf][0] += __shfl_xor_sync(0xffffffffu, su[mf][0], 1);
            su[mf][0] += __shfl_xor_sync(0xffffffffu, su[mf][0], 2);
            su[mf][1] += __shfl_xor_sync(0xffffffffu, su[mf][1], 1);
            su[mf][1] += __shfl_xor_sync(0xffffffffu, su[mf][1], 2);
        }
        if ((lane & 3) == 0) {
            sume[r0q]      = su[0][0];
            sume[r0q + 8]  = su[0][1];
            sume[r0q + 16] = su[1][0];
            sume[r0q + 24] = su[1][1];
        }

        // ---- write P half (fp16) into exchange tile: [row, kh*32 + col] ----
        #pragma unroll
        for (int mf = 0; mf < 2; ++mf) {
            #pragma unroll
            for (int nb = 0; nb < 4; ++nb) {
                const int idx = mf * 4 + nb;
                uint32_t a0_ = sm0 + (uint32_t)(SM_P + (R0 + mf * 16 + r0q) * PRSB
                              + kh * 64 + ((nb << 3) + ((lane & 3) << 1)) * 2);
                uint32_t p0 = pack_h2(s[idx][0], s[idx][1]);
                uint32_t p1 = pack_h2(s[idx][2], s[idx][3]);
                asm volatile("st.shared.b32 [%0], %1;" :: "r"(a0_), "r"(p0));
                asm volatile("st.shared.b32 [%0], %1;" :: "r"(a0_ + 8 * PRSB), "r"(p1));
            }
        }
        __syncthreads();                        // sum + P exchange

        #pragma unroll
        for (int mf = 0; mf < 2; ++mf)
            #pragma unroll
            for (int h = 0; h < 2; ++h) {
                float stot = su[mf][h] + supr[r0q + mf * 16 + h * 8];
                lr[mf][h] = lr[mf][h] * aa[mf][h] + stot;
            }

        if (__ballot_sync(0xffffffffu,
                (aa[0][0] != 1.f) || (aa[0][1] != 1.f) || (aa[1][0] != 1.f) || (aa[1][1] != 1.f))) {
            #pragma unroll
            for (int mf = 0; mf < 2; ++mf)
                #pragma unroll
                for (int nd = 0; nd < 8; ++nd) {
                    acc[mf*8+nd][0] *= aa[mf][0]; acc[mf*8+nd][1] *= aa[mf][0];
                    acc[mf*8+nd][2] *= aa[mf][1]; acc[mf*8+nd][3] *= aa[mf][1];
                }
        }

        // ---- O(32 rows x 64 dims) += P(32 x 64 full keys) V(64 x 64 dim-half) ----
        const uint32_t vfb = vf_l + (uint32_t)((kt & 1) * PLANE);
        #pragma unroll
        for (int kb = 0; kb < 4; ++kb) {
            uint32_t pa0[4], pa1[4];
            ldsm4(pa0, pfrag[0] + kb * 32);
            ldsm4(pa1, pfrag[1] + kb * 32);
            const uint32_t va = vfb + (uint32_t)(kb * 16 * RSB);
            #pragma unroll
            for (int jp = 0; jp < 4; ++jp) {
                uint32_t bv[4];
                ldsm4t(bv, va + jp * 32);
                mma_f16(acc[jp*2],     pa0, bv[0], bv[1]);
                mma_f16(acc[jp*2+1],   pa0, bv[2], bv[3]);
                mma_f16(acc[8+jp*2],   pa1, bv[0], bv[1]);
                mma_f16(acc[8+jp*2+1], pa1, bv[2], bv[3]);
            }
        }
    }

    // ---- epilogue: rows R0 + mf*16 + r0q (+8), dims kh*64 + ... ----
    #pragma unroll
    for (int mf = 0; mf < 2; ++mf) {
        float inv0 = (lr[mf][0] > 0.f) ? (1.0f / lr[mf][0]) : 0.f;
        float inv1 = (lr[mf][1] > 0.f) ? (1.0f / lr[mf][1]) : 0.f;
        const size_t gr0 = (size_t)b * LQ_ + q0 + R0 + mf * 16 + r0q;
        const size_t gr1 = gr0 + 8;
        #pragma unroll
        for (int nd = 0; nd < 8; ++nd) {
            int col = kh * 64 + nd * 8 + ((lane & 3) << 1);
            float2 o0 = make_float2(acc[mf*8+nd][0] * inv0, acc[mf*8+nd][1] * inv0);
            float2 o1 = make_float2(acc[mf*8+nd][2] * inv1, acc[mf*8+nd][3] * inv1);
            *(float2*)(og + gr0 * DH + col) = o0;
            *(float2*)(og + gr1 * DH + col) = o1;
        }
    }
}

} // namespace

extern "C" void kernel_launch(void* const* d_in, const int* in_sizes, int n_in,
                              void* d_out, int out_size) {
    const float* q = (const float*)d_in[0];
    const float* k = (const float*)d_in[1];
    const float* v = (const float*)d_in[2];
    const uint32_t* mask = (const uint32_t*)d_in[3];
    float* out = (float*)d_out;
    (void)in_sizes; (void)n_in; (void)out_size;

    conv_kernel<<<8192, 256>>>(k, v);

    cudaFuncSetAttribute(fa_r16_kernel, cudaFuncAttributeMaxDynamicSharedMemorySize, SM_TOT);
    dim3 grid(LQ_ / BR, B_);
    fa_r16_kernel<<<grid, NTH, SM_TOT>>>(q, mask, out);
}